// round 1
// baseline (speedup 1.0000x reference)
#include <cuda_runtime.h>
#include <math.h>

#define AA 48
#define NDP 1128        // nondiag pairs
#define STEPS 23
#define ROW 1176        // AA + NDP
#define BPB 4           // batches per block
#define THREADS 256

__device__ float g_nd[NDP * 6];   // per-pair 6-entry LUT: [0,f6,f8,f9,f12,1]
__device__ float g_dg[AA * 3];    // per-diag 3-entry LUT: [0, sig, 1]
__device__ int   g_pair[NDP];     // iy | (ix<<8)

__global__ void setup_kernel(const float* __restrict__ ed,
                             const float* __restrict__ en) {
    int k = blockIdx.x * blockDim.x + threadIdx.x;
    if (k < AA) {
        float s = 1.f / (1.f + expf(-ed[k]));
        g_dg[k * 3 + 0] = 0.f;
        g_dg[k * 3 + 1] = s;
        g_dg[k * 3 + 2] = 1.f;
    }
    if (k < NDP) {
        float f12 = 1.f / (1.f + expf(-en[k * 4 + 0]));
        float f9  = 1.f / (1.f + expf(-en[k * 4 + 1])) * f12;
        float f8  = 1.f / (1.f + expf(-en[k * 4 + 2])) * f9;
        float f6  = 1.f / (1.f + expf(-en[k * 4 + 3])) * f8;
        g_nd[k * 6 + 0] = 0.f;
        g_nd[k * 6 + 1] = f6;
        g_nd[k * 6 + 2] = f8;
        g_nd[k * 6 + 3] = f9;
        g_nd[k * 6 + 4] = f12;
        g_nd[k * 6 + 5] = 1.f;
        // pair k -> (iy, ix) in row-major upper triangle, ix > iy
        int rem = k, iy = 0;
        while (rem >= AA - 1 - iy) { rem -= AA - 1 - iy; ++iy; }
        int ix = iy + 1 + rem;
        g_pair[k] = iy | (ix << 8);
    }
}

__global__ __launch_bounds__(THREADS)
void main_kernel(const int* __restrict__ x, float* __restrict__ out) {
    __shared__ float s_nd[NDP * 6];            // 27072 B
    __shared__ float s_dg[AA * 3];             //   576 B
    __shared__ int   s_pair[NDP];              //  4512 B
    __shared__ unsigned char s_u[BPB][STEPS][AA]; // 4416 B

    const int tid = threadIdx.x;
    for (int i = tid; i < NDP * 6; i += THREADS) s_nd[i] = g_nd[i];
    for (int i = tid; i < AA * 3;  i += THREADS) s_dg[i] = g_dg[i];
    for (int i = tid; i < NDP;     i += THREADS) s_pair[i] = g_pair[i];

    const int b0 = blockIdx.x * BPB;

    // ---- integer recurrence: one thread per (batch-in-block, column) ----
    if (tid < BPB * AA) {
        int q = tid / AA;
        int j = tid - q * AA;
        const int* xb = x + (long)(b0 + q) * (25 * AA) + j;
        unsigned int v = 0;
        #pragma unroll
        for (int r = 0; r < 25; ++r)
            v |= ((unsigned int)__ldg(xb + r * AA)) << r;

        int st = -1, dt = 1;
        #pragma unroll
        for (int r = 0; r < STEPS; ++r) {
            int a  = (v >> r)       & 1;
            int bb = (v >> (r + 1)) & 1;
            int c  = (v >> (r + 2)) & 1;
            int de = a ^ c;                          // a + c - 2ac
            int me = bb * (1 - (a + c)) + a * c;
            dt = dt * (1 - 2 * me);
            st = st + dt * de;
            st = st < -1 ? -1 : (st > 1 ? 1 : st);
            int ome = 1 - me;
            dt = dt * (1 - st * st * ome) - st * ome;
            s_u[q][r][j] = (unsigned char)(st + 1);  // 0,1,2
        }
    }
    __syncthreads();

    // ---- output phase: 294 float4 per row, coalesced streaming stores ----
    int k4 = tid;
    for (int pass = 0; pass < 2; ++pass, k4 += THREADS) {
        if (k4 >= ROW / 4) break;
        const int k0 = k4 * 4;
        const bool isdiag = (k4 < AA / 4);  // first 12 float4s are diag-only

        int ii[4], jj[4], tb[4];
        #pragma unroll
        for (int e = 0; e < 4; ++e) {
            int k = k0 + e;
            if (isdiag) {
                jj[e] = k; ii[e] = 0; tb[e] = 0;
            } else {
                int kp = k - AA;
                int p  = s_pair[kp];
                ii[e]  = p & 255;
                jj[e]  = p >> 8;
                tb[e]  = kp * 6;
            }
        }

        for (int q = 0; q < BPB; ++q) {
            float* orow = out + (long)(b0 + q) * (STEPS * ROW) + k0;
            for (int r = 0; r < STEPS; ++r) {
                const unsigned char* u = s_u[q][r];
                float vv[4];
                #pragma unroll
                for (int e = 0; e < 4; ++e) {
                    if (isdiag) {
                        vv[e] = s_dg[jj[e] * 3 + (int)u[jj[e]]];
                    } else {
                        int ui = u[ii[e]];
                        int uj = u[jj[e]];
                        int cls = ui + uj + ((ui * uj) != 0 ? 1 : 0);
                        vv[e] = s_nd[tb[e] + cls];
                    }
                }
                float4 v4 = make_float4(vv[0], vv[1], vv[2], vv[3]);
                __stcs(reinterpret_cast<float4*>(orow + (long)r * ROW), v4);
            }
        }
    }
}

extern "C" void kernel_launch(void* const* d_in, const int* in_sizes, int n_in,
                              void* d_out, int out_size) {
    const int*   x  = (const int*)d_in[0];     // (4096, 25, 48) int32
    const float* ed = (const float*)d_in[1];   // (1, 48) f32
    const float* en = (const float*)d_in[2];   // (1, 1128, 4) f32
    float* out = (float*)d_out;                // (4096, 23, 1176) f32

    setup_kernel<<<(NDP + 255) / 256, 256>>>(ed, en);
    int nb = in_sizes[0] / (25 * AA);          // 4096 batches
    main_kernel<<<nb / BPB, THREADS>>>(x, out);
}